// round 15
// baseline (speedup 1.0000x reference)
#include <cuda_runtime.h>
#include <cuda.h>
#include <cuda_bf16.h>
#include <cstdint>

#define BB 8
#define SS 2048
#define NN 8
#define DD 768
#define ROWS (BB*SS)          // 16384
#define CHUNKS 8
#define CROWS (ROWS/CHUNKS)   // 2048

__device__ __align__(256) float         g_U[ROWS*DD];
__device__ __align__(256) float         g_ctx[ROWS*DD];    // tf32-rounded
__device__ __align__(256) __nv_bfloat16 g_qb[ROWS*DD];
__device__ __align__(256) __nv_bfloat16 g_Wppb[DD*DD];     // [n,k] bf16
__device__ __align__(256) float         g_Wpp[DD*DD];      // fp32 staging
__device__ __align__(256) float         g_WkT32[DD*DD];    // Wk^T tf32-rounded
__device__ __align__(256) float         g_WqT32[DD*DD];    // Wq^T tf32-rounded
__device__ __align__(256) float         g_Wv32[DD*DD];     // Wv tf32-rounded
__device__ __align__(256) float         g_bp[DD];

// ======================= portable PTX helpers (<= sm_90) ====================
__device__ __forceinline__ uint32_t smem_u32(const void* p) {
    uint32_t a;
    asm("{ .reg .u64 t; cvta.to.shared.u64 t, %1; cvt.u32.u64 %0, t; }"
        : "=r"(a) : "l"(p));
    return a;
}

#define MBAR_INIT(addr, cnt) \
    asm volatile("mbarrier.init.shared.b64 [%0], %1;" :: "r"((uint32_t)(addr)), "r"((uint32_t)(cnt)) : "memory")
#define MBAR_EXPECT_TX(addr, bytes) \
    asm volatile("mbarrier.arrive.expect_tx.shared.b64 _, [%0], %1;" \
                 :: "r"((uint32_t)(addr)), "r"((uint32_t)(bytes)) : "memory")

#define MBAR_WAIT(mbar_addr, phase_parity) do {                                   \
    uint32_t _mbar = (uint32_t)(mbar_addr);                                        \
    uint32_t _par  = (uint32_t)(phase_parity);                                     \
    uint32_t _done;                                                                \
    asm volatile(                                                                  \
        "{\n\t.reg .pred p;\n\t"                                                   \
        "mbarrier.try_wait.parity.acquire.cta.shared::cta.b64 p, [%1], %2;\n\t"    \
        "selp.b32 %0, 1, 0, p;\n\t}"                                               \
        : "=r"(_done) : "r"(_mbar), "r"(_par) : "memory");                         \
    if (!_done) {                                                                  \
        asm volatile(                                                              \
            "{\n\t.reg .pred P1;\n\t"                                              \
            "WAIT_LOOP_%=:\n\t"                                                    \
            "mbarrier.try_wait.parity.acquire.cta.shared::cta.b64 P1, [%0], %1, 0x989680;\n\t" \
            "@P1 bra.uni WAIT_DONE_%=;\n\t"                                        \
            "bra.uni WAIT_LOOP_%=;\n\t"                                            \
            "WAIT_DONE_%=:\n\t}"                                                   \
            :: "r"(_mbar), "r"(_par) : "memory");                                  \
    }                                                                              \
} while (0)

#define TMA_2D(dst, map, x, y, mbar) \
    asm volatile("cp.async.bulk.tensor.2d.shared::cluster.global.tile.mbarrier::complete_tx::bytes " \
        "[%0], [%1, {%2, %3}], [%4];" \
        :: "r"((uint32_t)(dst)), "l"(map), "r"((int)(x)), "r"((int)(y)), \
           "r"((uint32_t)(mbar)) : "memory")

#define LDSM_X4(r0, r1, r2, r3, addr) \
    asm volatile("ldmatrix.sync.aligned.m8n8.x4.shared.b16 {%0,%1,%2,%3}, [%4];" \
        : "=r"(r0), "=r"(r1), "=r"(r2), "=r"(r3) : "r"((uint32_t)(addr)))

#define MMA_BF16(d, a, b) \
    asm volatile("mma.sync.aligned.m16n8k16.row.col.f32.bf16.bf16.f32 " \
        "{%0,%1,%2,%3}, {%4,%5,%6,%7}, {%8,%9}, {%0,%1,%2,%3};" \
        : "+f"((d)[0]), "+f"((d)[1]), "+f"((d)[2]), "+f"((d)[3]) \
        : "r"((a)[0]), "r"((a)[1]), "r"((a)[2]), "r"((a)[3]), \
          "r"((b)[0]), "r"((b)[1]))

#define MMA_TF32(d, a, b) \
    asm volatile("mma.sync.aligned.m16n8k8.row.col.f32.tf32.tf32.f32 " \
        "{%0,%1,%2,%3}, {%4,%5,%6,%7}, {%8,%9}, {%0,%1,%2,%3};" \
        : "+f"((d)[0]), "+f"((d)[1]), "+f"((d)[2]), "+f"((d)[3]) \
        : "r"((a)[0]), "r"((a)[1]), "r"((a)[2]), "r"((a)[3]), \
          "r"((b)[0]), "r"((b)[1]))

__device__ __forceinline__ float tf32r(float f) {
    uint32_t u;
    asm("cvt.rna.tf32.f32 %0, %1;" : "=r"(u) : "f"(f));
    return __uint_as_float(u);
}

// Pipeline: 3 stages x (16KB A + 16KB B); syncthreads-gated reuse.
#define ST 3
#define STB 32768
#define GSMEM (1024 + ST * STB)

// ===========================================================================
// GEMM1 (bf16): C[rows,768] = A @ B^T (+bias). Tile 128x128, K-chunk 64.
// ===========================================================================
__global__ __launch_bounds__(256, 2) void gemm1_bf16_tma(
    const __grid_constant__ CUtensorMap mA,
    const __grid_constant__ CUtensorMap mB,
    float* __restrict__ C, const float* __restrict__ bias, int rowOff)
{
    extern __shared__ __align__(1024) char smem[];
    const uint32_t sb = smem_u32(smem);
    const int tid = threadIdx.x, lane = tid & 31, wid = tid >> 5;
    const int wm = wid & 3, wn = wid >> 2;
    const int bm = rowOff + blockIdx.y * 128, bn = blockIdx.x * 128;
    const uint32_t fullb = sb;
    const uint32_t tiles = sb + 1024;
    const int NCH = 12;

    if (tid == 0) {
        #pragma unroll
        for (int s = 0; s < ST; s++) MBAR_INIT(fullb + 8*s, 1);
        asm volatile("fence.proxy.async.shared::cta;" ::: "memory");
    }
    __syncthreads();

    if (tid == 0) {
        #pragma unroll
        for (int s = 0; s < ST - 1; s++) {
            MBAR_EXPECT_TX(fullb + 8*s, STB);
            uint32_t dA = tiles + s * STB;
            TMA_2D(dA,         &mA, s * 64, bm, fullb + 8*s);
            TMA_2D(dA + 16384, &mB, s * 64, bn, fullb + 8*s);
        }
    }

    float d[2][8][4];
    #pragma unroll
    for (int i = 0; i < 2; i++)
        #pragma unroll
        for (int j = 0; j < 8; j++)
            #pragma unroll
            for (int k = 0; k < 4; k++) d[i][j][k] = 0.f;

    for (int it = 0; it < NCH; it++) {
        if (tid == 0) {
            int pre = it + ST - 1;
            if (pre < NCH) {
                int sp = pre % ST;
                MBAR_EXPECT_TX(fullb + 8*sp, STB);
                uint32_t dA = tiles + sp * STB;
                TMA_2D(dA,         &mA, pre * 64, bm, fullb + 8*sp);
                TMA_2D(dA + 16384, &mB, pre * 64, bn, fullb + 8*sp);
            }
        }
        int s = it % ST;
        MBAR_WAIT(fullb + 8*s, (it / ST) & 1);
        uint32_t sA = tiles + s * STB;
        uint32_t sB = sA + 16384;

        #pragma unroll
        for (int ks = 0; ks < 4; ks++) {
            uint32_t col = (uint32_t)(ks * 32 + ((lane >> 4) << 4));
            uint32_t a[2][4];
            #pragma unroll
            for (int i = 0; i < 2; i++) {
                int m = wm * 32 + i * 16 + (lane & 15);
                uint32_t addr = sA + (uint32_t)m * 128 + (col ^ (uint32_t)((m & 7) * 16));
                LDSM_X4(a[i][0], a[i][1], a[i][2], a[i][3], addr);
            }
            uint32_t b[8][2];
            #pragma unroll
            for (int jj = 0; jj < 4; jj++) {
                int n = wn * 64 + jj * 16 + (lane & 15);
                uint32_t addr = sB + (uint32_t)n * 128 + (col ^ (uint32_t)((n & 7) * 16));
                uint32_t r0, r1, r2, r3;
                LDSM_X4(r0, r1, r2, r3, addr);
                b[2*jj][0] = r0;   b[2*jj][1] = r2;
                b[2*jj+1][0] = r1; b[2*jj+1][1] = r3;
            }
            #pragma unroll
            for (int i = 0; i < 2; i++)
                #pragma unroll
                for (int j = 0; j < 8; j++)
                    MMA_BF16(d[i][j], a[i], b[j]);
        }
        __syncthreads();   // stage s free for reuse; gates next prefetch
    }

    #pragma unroll
    for (int i = 0; i < 2; i++) {
        int r0 = bm + wm * 32 + i * 16 + (lane >> 2);
        #pragma unroll
        for (int j = 0; j < 8; j++) {
            int gc = bn + wn * 64 + j * 8 + (lane & 3) * 2;
            float2 bv = bias ? *(const float2*)&bias[gc] : make_float2(0.f, 0.f);
            *(float2*)&C[(size_t)r0 * DD + gc] =
                make_float2(d[i][j][0] + bv.x, d[i][j][1] + bv.y);
            *(float2*)&C[(size_t)(r0 + 8) * DD + gc] =
                make_float2(d[i][j][2] + bv.x, d[i][j][3] + bv.y);
        }
    }
}

// ===========================================================================
// GEMM2 (tf32, ldmatrix): C[rows,768] = A @ B^T (+addmat). Tile 128x128, NCH=24.
// ===========================================================================
__global__ __launch_bounds__(256, 2) void gemm2_tf32_tma(
    const __grid_constant__ CUtensorMap mA,
    const __grid_constant__ CUtensorMap mB,
    float* __restrict__ C, const float* __restrict__ addmat, int rowOff)
{
    extern __shared__ __align__(1024) char smem[];
    const uint32_t sb = smem_u32(smem);
    const int tid = threadIdx.x, lane = tid & 31, wid = tid >> 5;
    const int wm = wid & 3, wn = wid >> 2;
    const int bm = rowOff + blockIdx.y * 128, bn = blockIdx.x * 128;
    const uint32_t fullb = sb;
    const uint32_t tiles = sb + 1024;
    const int NCH = 24;
    const int lt = lane >> 3;   // ldmatrix tile index 0..3
    const int lr = lane & 7;    // row within tile

    if (tid == 0) {
        #pragma unroll
        for (int s = 0; s < ST; s++) MBAR_INIT(fullb + 8*s, 1);
        asm volatile("fence.proxy.async.shared::cta;" ::: "memory");
    }
    __syncthreads();

    if (tid == 0) {
        #pragma unroll
        for (int s = 0; s < ST - 1; s++) {
            MBAR_EXPECT_TX(fullb + 8*s, STB);
            uint32_t dA = tiles + s * STB;
            TMA_2D(dA,         &mA, s * 32, bm, fullb + 8*s);
            TMA_2D(dA + 16384, &mB, s * 32, bn, fullb + 8*s);
        }
    }

    float d[2][8][4];
    #pragma unroll
    for (int i = 0; i < 2; i++)
        #pragma unroll
        for (int j = 0; j < 8; j++)
            #pragma unroll
            for (int k = 0; k < 4; k++) d[i][j][k] = 0.f;

    for (int it = 0; it < NCH; it++) {
        if (tid == 0) {
            int pre = it + ST - 1;
            if (pre < NCH) {
                int sp = pre % ST;
                MBAR_EXPECT_TX(fullb + 8*sp, STB);
                uint32_t dA = tiles + sp * STB;
                TMA_2D(dA,         &mA, pre * 32, bm, fullb + 8*sp);
                TMA_2D(dA + 16384, &mB, pre * 32, bn, fullb + 8*sp);
            }
        }
        int s = it % ST;
        MBAR_WAIT(fullb + 8*s, (it / ST) & 1);
        uint32_t sA = tiles + s * STB;
        uint32_t sB = sA + 16384;

        // 8x8 b16 ldmatrix tile == 8x4 fp32 tile; per-thread layout matches
        // the tf32 m16n8k8 fragment exactly.
        #pragma unroll
        for (int ks = 0; ks < 4; ks++) {
            uint32_t a[2][4];
            #pragma unroll
            for (int i = 0; i < 2; i++) {
                int m = wm * 32 + i * 16 + (lt & 1) * 8 + lr;
                uint32_t col = (uint32_t)(ks * 32 + (lt >> 1) * 16);
                uint32_t addr = sA + (uint32_t)m * 128 + (col ^ (uint32_t)((m & 7) * 16));
                LDSM_X4(a[i][0], a[i][1], a[i][2], a[i][3], addr);
            }
            uint32_t b[8][2];
            #pragma unroll
            for (int jj = 0; jj < 4; jj++) {
                int n = wn * 64 + jj * 16 + (lt >> 1) * 8 + lr;
                uint32_t col = (uint32_t)(ks * 32 + (lt & 1) * 16);
                uint32_t addr = sB + (uint32_t)n * 128 + (col ^ (uint32_t)((n & 7) * 16));
                uint32_t r0, r1, r2, r3;
                LDSM_X4(r0, r1, r2, r3, addr);
                b[2*jj][0] = r0;   b[2*jj][1] = r1;
                b[2*jj+1][0] = r2; b[2*jj+1][1] = r3;
            }
            #pragma unroll
            for (int i = 0; i < 2; i++)
                #pragma unroll
                for (int j = 0; j < 8; j++)
                    MMA_TF32(d[i][j], a[i], b[j]);
        }
        __syncthreads();
    }

    #pragma unroll
    for (int i = 0; i < 2; i++) {
        int r0 = bm + wm * 32 + i * 16 + (lane >> 2);
        #pragma unroll
        for (int j = 0; j < 8; j++) {
            int gc = bn + wn * 64 + j * 8 + (lane & 3) * 2;
            float2 a0 = make_float2(0.f, 0.f), a1 = make_float2(0.f, 0.f);
            if (addmat) {
                a0 = *(const float2*)&addmat[(size_t)r0 * DD + gc];
                a1 = *(const float2*)&addmat[(size_t)(r0 + 8) * DD + gc];
            }
            *(float2*)&C[(size_t)r0 * DD + gc] =
                make_float2(d[i][j][0] + a0.x, d[i][j][1] + a0.y);
            *(float2*)&C[(size_t)(r0 + 8) * DD + gc] =
                make_float2(d[i][j][2] + a1.x, d[i][j][3] + a1.y);
        }
    }
}

// ---------------------------------------------------------------------------
__global__ void prep_bp_kernel(const float* __restrict__ bq,
                               const float* __restrict__ Wk,
                               float* __restrict__ bp) {
    int n = blockIdx.x * blockDim.x + threadIdx.x;
    if (n >= DD) return;
    float acc = 0.f;
    #pragma unroll 4
    for (int i = 0; i < DD; i++) acc += bq[i] * Wk[i * DD + n];
    bp[n] = acc;
}

// fp32 -> bf16 elementwise (float4-wide)
__global__ void convb_kernel(const float4* __restrict__ in,
                             uint2* __restrict__ out, int n4) {
    int i = blockIdx.x * blockDim.x + threadIdx.x;
    if (i >= n4) return;
    float4 v = in[i];
    __nv_bfloat162 p0 = __floats2bfloat162_rn(v.x, v.y);
    __nv_bfloat162 p1 = __floats2bfloat162_rn(v.z, v.w);
    out[i] = make_uint2(*(uint32_t*)&p0, *(uint32_t*)&p1);
}

// fp32 -> tf32-rounded fp32 elementwise
__global__ void convt_kernel(const float4* __restrict__ in,
                             float4* __restrict__ out, int n4) {
    int i = blockIdx.x * blockDim.x + threadIdx.x;
    if (i >= n4) return;
    float4 v = in[i];
    out[i] = make_float4(tf32r(v.x), tf32r(v.y), tf32r(v.z), tf32r(v.w));
}

// transpose 768x768 + tf32 rounding (fp32 out)
__global__ void tconvt_kernel(const float* __restrict__ in,
                              float* __restrict__ out) {
    __shared__ float t[32][33];
    int bx = blockIdx.x * 32, by = blockIdx.y * 32;
    int tx = threadIdx.x, ty = threadIdx.y;   // 32 x 8
    #pragma unroll
    for (int i = 0; i < 4; i++)
        t[ty + i * 8][tx] = in[(size_t)(by + ty + i * 8) * DD + bx + tx];
    __syncthreads();
    #pragma unroll
    for (int i = 0; i < 4; i++)
        out[(size_t)(bx + ty + i * 8) * DD + by + tx] =
            tf32r(t[tx][ty + i * 8]);
}

// ---------------------------------------------------------------------------
// Attention: 192 threads, float4 lanes. ctx written tf32-rounded.
// ---------------------------------------------------------------------------
__global__ __launch_bounds__(192) void attn_kernel(
    const float* __restrict__ U,
    const float* __restrict__ key,
    const float* __restrict__ value,
    float* __restrict__ probs_out,
    float* __restrict__ ctx, int rowOff)
{
    const int row = rowOff + blockIdx.x;
    const int tid = threadIdx.x;               // 0..191
    const float4* u4 = (const float4*)(U + (size_t)row * DD);
    const float4* k4 = (const float4*)(key + (size_t)row * NN * DD);
    const float4* v4 = (const float4*)(value + (size_t)row * NN * DD);

    const float4 u = u4[tid];

    float p[NN];
    #pragma unroll
    for (int n = 0; n < NN; n++) {
        float4 k = k4[n * 192 + tid];
        p[n] = u.x * k.x + u.y * k.y + u.z * k.z + u.w * k.w;
    }
    #pragma unroll
    for (int n = 0; n < NN; n++)
        #pragma unroll
        for (int off = 16; off > 0; off >>= 1)
            p[n] += __shfl_down_sync(0xffffffffu, p[n], off);

    __shared__ float red[6][NN];
    __shared__ float probs[NN];
    const int lane = tid & 31, w = tid >> 5;
    if (lane == 0) {
        #pragma unroll
        for (int n = 0; n < NN; n++) red[w][n] = p[n];
    }
    __syncthreads();

    if (tid == 0) {
        float s[NN];
        #pragma unroll
        for (int n = 0; n < NN; n++) {
            float acc = 0.f;
            #pragma unroll
            for (int ww = 0; ww < 6; ww++) acc += red[ww][n];
            s[n] = acc;
        }
        float m = s[0];
        #pragma unroll
        for (int n = 1; n < NN; n++) m = fmaxf(m, s[n]);
        float e[NN], sum = 0.f;
        #pragma unroll
        for (int n = 0; n < NN; n++) { e[n] = expf((s[n] - m) * (1.0f / 50.0f)); sum += e[n]; }
        float inv = 1.f / sum;
        #pragma unroll
        for (int n = 0; n < NN; n++) probs[n] = e[n] * inv;
    }
    __syncthreads();

    if (tid < NN) probs_out[(size_t)row * NN + tid] = probs[tid];

    float pr[NN];
    #pragma unroll
    for (int n = 0; n < NN; n++) pr[n] = probs[n];

    float4 acc = make_float4(0.f, 0.f, 0.f, 0.f);
    #pragma unroll
    for (int n = 0; n < NN; n++) {
        float4 v = v4[n * 192 + tid];
        acc.x += pr[n] * v.x; acc.y += pr[n] * v.y;
        acc.z += pr[n] * v.z; acc.w += pr[n] * v.w;
    }
    ((float4*)(ctx + (size_t)row * DD))[tid] =
        make_float4(tf32r(acc.x), tf32r(acc.y), tf32r(acc.z), tf32r(acc.w));
}

// ---------------------------------------------------------------------------
typedef CUresult (*EncodeFn)(CUtensorMap*, CUtensorMapDataType, cuuint32_t, void*,
                             const cuuint64_t*, const cuuint64_t*, const cuuint32_t*,
                             const cuuint32_t*, CUtensorMapInterleave, CUtensorMapSwizzle,
                             CUtensorMapL2promotion, CUtensorMapFloatOOBfill);

static void make_map2d(EncodeFn enc, CUtensorMap* m, void* ptr,
                       CUtensorMapDataType dt, int elsz,
                       uint64_t d0, uint64_t d1, uint32_t b0, uint32_t b1) {
    cuuint64_t dims[2]    = {d0, d1};
    cuuint64_t strides[1] = {d0 * (uint64_t)elsz};
    cuuint32_t box[2]     = {b0, b1};
    cuuint32_t es[2]      = {1, 1};
    enc(m, dt, 2, ptr, dims, strides, box, es,
        CU_TENSOR_MAP_INTERLEAVE_NONE, CU_TENSOR_MAP_SWIZZLE_128B,
        CU_TENSOR_MAP_L2_PROMOTION_L2_128B, CU_TENSOR_MAP_FLOAT_OOB_FILL_NONE);
}

extern "C" void kernel_launch(void* const* d_in, const int* in_sizes, int n_in,
                              void* d_out, int out_size) {
    const float* query    = (const float*)d_in[0];
    const float* key      = (const float*)d_in[1];
    const float* value    = (const float*)d_in[2];
    const float* residual = (const float*)d_in[3];
    const float* Wq       = (const float*)d_in[4];
    const float* bq       = (const float*)d_in[5];
    const float* Wk       = (const float*)d_in[6];
    // d_in[7] = bk: constant logit shift across heads -> dropped by softmax
    const float* Wv       = (const float*)d_in[8];

    float* out       = (float*)d_out;
    float* probs_out = out;
    float* ctx_out   = out + (size_t)ROWS * NN;

    float *U, *ctx, *Wpp, *WkT32, *WqT32, *Wv32, *bp;
    __nv_bfloat16 *qb, *Wppb;
    cudaGetSymbolAddress((void**)&U,     g_U);
    cudaGetSymbolAddress((void**)&ctx,   g_ctx);
    cudaGetSymbolAddress((void**)&qb,    g_qb);
    cudaGetSymbolAddress((void**)&Wppb,  g_Wppb);
    cudaGetSymbolAddress((void**)&Wpp,   g_Wpp);
    cudaGetSymbolAddress((void**)&WkT32, g_WkT32);
    cudaGetSymbolAddress((void**)&WqT32, g_WqT32);
    cudaGetSymbolAddress((void**)&Wv32,  g_Wv32);
    cudaGetSymbolAddress((void**)&bp,    g_bp);

    cudaFuncSetAttribute(gemm1_bf16_tma,
                         cudaFuncAttributeMaxDynamicSharedMemorySize, GSMEM);
    cudaFuncSetAttribute(gemm2_tf32_tma,
                         cudaFuncAttributeMaxDynamicSharedMemorySize, GSMEM);

    EncodeFn enc = nullptr;
    cudaDriverEntryPointQueryResult qr;
    cudaGetDriverEntryPointByVersion("cuTensorMapEncodeTiled", (void**)&enc,
                                     12000, cudaEnableDefault, &qr);

    CUtensorMap mQ, mWpp, mCtx, mWv, mWkT, mWqT;
    make_map2d(enc, &mQ,   qb,    CU_TENSOR_MAP_DATA_TYPE_BFLOAT16, 2, DD, ROWS, 64, 128);
    make_map2d(enc, &mWpp, Wppb,  CU_TENSOR_MAP_DATA_TYPE_BFLOAT16, 2, DD, DD,   64, 128);
    make_map2d(enc, &mWkT, WkT32, CU_TENSOR_MAP_DATA_TYPE_FLOAT32,  4, DD, DD,   32, 128);
    make_map2d(enc, &mWqT, WqT32, CU_TENSOR_MAP_DATA_TYPE_FLOAT32,  4, DD, DD,   32, 128);
    make_map2d(enc, &mCtx, ctx,   CU_TENSOR_MAP_DATA_TYPE_FLOAT32,  4, DD, ROWS, 32, 128);
    make_map2d(enc, &mWv,  Wv32,  CU_TENSOR_MAP_DATA_TYPE_FLOAT32,  4, DD, DD,   32, 128);

    // Streams + events. Created on the first (uncaptured, correctness) call;
    // reused afterwards. Capture rule: a side stream joins the capture ONLY
    // via StreamWaitEvent on an event recorded in a captured stream — so we
    // fork sAux/sG2 from stream 0 with evRoot BEFORE launching on them.
    static cudaStream_t sAttn = nullptr, sG2 = nullptr, sAux = nullptr;
    static cudaEvent_t evG1[CHUNKS], evA[CHUNKS], evRoot, evQ, evDone;
    if (!sAttn) {
        int loPrio, hiPrio;
        cudaDeviceGetStreamPriorityRange(&loPrio, &hiPrio);
        cudaStreamCreateWithFlags(&sAttn, cudaStreamNonBlocking);
        cudaStreamCreateWithPriority(&sG2, cudaStreamNonBlocking, hiPrio);
        cudaStreamCreateWithFlags(&sAux, cudaStreamNonBlocking);
        for (int i = 0; i < CHUNKS; i++) {
            cudaEventCreateWithFlags(&evG1[i], cudaEventDisableTiming);
            cudaEventCreateWithFlags(&evA[i],  cudaEventDisableTiming);
        }
        cudaEventCreateWithFlags(&evRoot, cudaEventDisableTiming);
        cudaEventCreateWithFlags(&evQ,    cudaEventDisableTiming);
        cudaEventCreateWithFlags(&evDone, cudaEventDisableTiming);
    }

    dim3 tgrid(DD / 32, DD / 32);

    // ---- fork side streams from the capture origin ----
    cudaEventRecord(evRoot, 0);
    cudaStreamWaitEvent(sAux, evRoot, 0);
    cudaStreamWaitEvent(sG2,  evRoot, 0);

    // sAux: query -> bf16 (gemm1's A operand)
    convb_kernel<<<(ROWS * DD / 4 + 255) / 256, 256, 0, sAux>>>(
        (const float4*)query, (uint2*)qb, ROWS * DD / 4);
    cudaEventRecord(evQ, sAux);

    // sG2: Wv tf32-round (only consumer is gemm2, same stream -> ordered)
    convt_kernel<<<(DD * DD / 4 + 255) / 256, 256, 0, sG2>>>(
        (const float4*)Wv, (float4*)Wv32, DD * DD / 4);

    // stream 0: bp + W'' chain (gemm1's other inputs)
    prep_bp_kernel<<<6, 128>>>(bq, Wk, bp);
    tconvt_kernel<<<tgrid, dim3(32, 8)>>>(Wk, WkT32);
    tconvt_kernel<<<tgrid, dim3(32, 8)>>>(Wq, WqT32);
    gemm2_tf32_tma<<<dim3(6, 6), 256, GSMEM>>>(mWkT, mWqT, Wpp, nullptr, 0);
    convb_kernel<<<(DD * DD / 4 + 255) / 256, 256>>>(
        (const float4*)Wpp, (uint2*)Wppb, DD * DD / 4);
    cudaStreamWaitEvent(0, evQ, 0);   // qb ready before first gemm1

    // ---- pipelined chunks: gemm1_i (0) -> attn_i (sAttn) -> gemm2_i (sG2)
    for (int i = 0; i < CHUNKS; i++) {
        int ro = i * CROWS;
        gemm1_bf16_tma<<<dim3(6, CROWS / 128), 256, GSMEM>>>(mQ, mWpp, U, bp, ro);
        cudaEventRecord(evG1[i], 0);

        cudaStreamWaitEvent(sAttn, evG1[i], 0);
        attn_kernel<<<CROWS, 192, 0, sAttn>>>(U, key, value, probs_out, ctx, ro);
        cudaEventRecord(evA[i], sAttn);

        cudaStreamWaitEvent(sG2, evA[i], 0);
        gemm2_tf32_tma<<<dim3(6, CROWS / 128), 256, GSMEM, sG2>>>(
            mCtx, mWv, ctx_out, residual, ro);
    }

    // join everything back to the default stream
    cudaEventRecord(evDone, sG2);
    cudaStreamWaitEvent(0, evDone, 0);
}

// round 16
// speedup vs baseline: 1.0423x; 1.0423x over previous
#include <cuda_runtime.h>
#include <cuda.h>
#include <cuda_bf16.h>
#include <cstdint>

#define BB 8
#define SS 2048
#define NN 8
#define DD 768
#define ROWS (BB*SS)          // 16384
#define CHUNKS 2
#define CROWS (ROWS/CHUNKS)   // 8192

__device__ __align__(256) float         g_U[ROWS*DD];
__device__ __align__(256) float         g_ctx[ROWS*DD];    // tf32-rounded
__device__ __align__(256) __nv_bfloat16 g_qb[ROWS*DD];
__device__ __align__(256) __nv_bfloat16 g_Wppb[DD*DD];     // [n,k] bf16
__device__ __align__(256) float         g_Wpp[DD*DD];      // fp32 staging
__device__ __align__(256) float         g_WkT32[DD*DD];    // Wk^T tf32-rounded
__device__ __align__(256) float         g_WqT32[DD*DD];    // Wq^T tf32-rounded
__device__ __align__(256) float         g_Wv32[DD*DD];     // Wv tf32-rounded
__device__ __align__(256) float         g_bp[DD];

// ======================= portable PTX helpers (<= sm_90) ====================
__device__ __forceinline__ uint32_t smem_u32(const void* p) {
    uint32_t a;
    asm("{ .reg .u64 t; cvta.to.shared.u64 t, %1; cvt.u32.u64 %0, t; }"
        : "=r"(a) : "l"(p));
    return a;
}

#define MBAR_INIT(addr, cnt) \
    asm volatile("mbarrier.init.shared.b64 [%0], %1;" :: "r"((uint32_t)(addr)), "r"((uint32_t)(cnt)) : "memory")
#define MBAR_EXPECT_TX(addr, bytes) \
    asm volatile("mbarrier.arrive.expect_tx.shared.b64 _, [%0], %1;" \
                 :: "r"((uint32_t)(addr)), "r"((uint32_t)(bytes)) : "memory")

#define MBAR_WAIT(mbar_addr, phase_parity) do {                                   \
    uint32_t _mbar = (uint32_t)(mbar_addr);                                        \
    uint32_t _par  = (uint32_t)(phase_parity);                                     \
    uint32_t _done;                                                                \
    asm volatile(                                                                  \
        "{\n\t.reg .pred p;\n\t"                                                   \
        "mbarrier.try_wait.parity.acquire.cta.shared::cta.b64 p, [%1], %2;\n\t"    \
        "selp.b32 %0, 1, 0, p;\n\t}"                                               \
        : "=r"(_done) : "r"(_mbar), "r"(_par) : "memory");                         \
    if (!_done) {                                                                  \
        asm volatile(                                                              \
            "{\n\t.reg .pred P1;\n\t"                                              \
            "WAIT_LOOP_%=:\n\t"                                                    \
            "mbarrier.try_wait.parity.acquire.cta.shared::cta.b64 P1, [%0], %1, 0x989680;\n\t" \
            "@P1 bra.uni WAIT_DONE_%=;\n\t"                                        \
            "bra.uni WAIT_LOOP_%=;\n\t"                                            \
            "WAIT_DONE_%=:\n\t}"                                                   \
            :: "r"(_mbar), "r"(_par) : "memory");                                  \
    }                                                                              \
} while (0)

#define TMA_2D(dst, map, x, y, mbar) \
    asm volatile("cp.async.bulk.tensor.2d.shared::cluster.global.tile.mbarrier::complete_tx::bytes " \
        "[%0], [%1, {%2, %3}], [%4];" \
        :: "r"((uint32_t)(dst)), "l"(map), "r"((int)(x)), "r"((int)(y)), \
           "r"((uint32_t)(mbar)) : "memory")

#define LDSM_X4(r0, r1, r2, r3, addr) \
    asm volatile("ldmatrix.sync.aligned.m8n8.x4.shared.b16 {%0,%1,%2,%3}, [%4];" \
        : "=r"(r0), "=r"(r1), "=r"(r2), "=r"(r3) : "r"((uint32_t)(addr)))

#define MMA_BF16(d, a, b) \
    asm volatile("mma.sync.aligned.m16n8k16.row.col.f32.bf16.bf16.f32 " \
        "{%0,%1,%2,%3}, {%4,%5,%6,%7}, {%8,%9}, {%0,%1,%2,%3};" \
        : "+f"((d)[0]), "+f"((d)[1]), "+f"((d)[2]), "+f"((d)[3]) \
        : "r"((a)[0]), "r"((a)[1]), "r"((a)[2]), "r"((a)[3]), \
          "r"((b)[0]), "r"((b)[1]))

#define MMA_TF32(d, a, b) \
    asm volatile("mma.sync.aligned.m16n8k8.row.col.f32.tf32.tf32.f32 " \
        "{%0,%1,%2,%3}, {%4,%5,%6,%7}, {%8,%9}, {%0,%1,%2,%3};" \
        : "+f"((d)[0]), "+f"((d)[1]), "+f"((d)[2]), "+f"((d)[3]) \
        : "r"((a)[0]), "r"((a)[1]), "r"((a)[2]), "r"((a)[3]), \
          "r"((b)[0]), "r"((b)[1]))

__device__ __forceinline__ float tf32r(float f) {
    uint32_t u;
    asm("cvt.rna.tf32.f32 %0, %1;" : "=r"(u) : "f"(f));
    return __uint_as_float(u);
}

// Pipeline: 3 stages x (16KB A + 16KB B); syncthreads-gated reuse.
#define ST 3
#define STB 32768
#define GSMEM (1024 + ST * STB)

// ===========================================================================
// GEMM1 (bf16): C[rows,768] = A @ B^T (+bias). Tile 128x128, K-chunk 64.
// ===========================================================================
__global__ __launch_bounds__(256, 2) void gemm1_bf16_tma(
    const __grid_constant__ CUtensorMap mA,
    const __grid_constant__ CUtensorMap mB,
    float* __restrict__ C, const float* __restrict__ bias, int rowOff)
{
    extern __shared__ __align__(1024) char smem[];
    const uint32_t sb = smem_u32(smem);
    const int tid = threadIdx.x, lane = tid & 31, wid = tid >> 5;
    const int wm = wid & 3, wn = wid >> 2;
    const int bm = rowOff + blockIdx.y * 128, bn = blockIdx.x * 128;
    const uint32_t fullb = sb;
    const uint32_t tiles = sb + 1024;
    const int NCH = 12;

    if (tid == 0) {
        #pragma unroll
        for (int s = 0; s < ST; s++) MBAR_INIT(fullb + 8*s, 1);
        asm volatile("fence.proxy.async.shared::cta;" ::: "memory");
    }
    __syncthreads();

    if (tid == 0) {
        #pragma unroll
        for (int s = 0; s < ST - 1; s++) {
            MBAR_EXPECT_TX(fullb + 8*s, STB);
            uint32_t dA = tiles + s * STB;
            TMA_2D(dA,         &mA, s * 64, bm, fullb + 8*s);
            TMA_2D(dA + 16384, &mB, s * 64, bn, fullb + 8*s);
        }
    }

    float d[2][8][4];
    #pragma unroll
    for (int i = 0; i < 2; i++)
        #pragma unroll
        for (int j = 0; j < 8; j++)
            #pragma unroll
            for (int k = 0; k < 4; k++) d[i][j][k] = 0.f;

    for (int it = 0; it < NCH; it++) {
        if (tid == 0) {
            int pre = it + ST - 1;
            if (pre < NCH) {
                int sp = pre % ST;
                MBAR_EXPECT_TX(fullb + 8*sp, STB);
                uint32_t dA = tiles + sp * STB;
                TMA_2D(dA,         &mA, pre * 64, bm, fullb + 8*sp);
                TMA_2D(dA + 16384, &mB, pre * 64, bn, fullb + 8*sp);
            }
        }
        int s = it % ST;
        MBAR_WAIT(fullb + 8*s, (it / ST) & 1);
        uint32_t sA = tiles + s * STB;
        uint32_t sB = sA + 16384;

        #pragma unroll
        for (int ks = 0; ks < 4; ks++) {
            uint32_t col = (uint32_t)(ks * 32 + ((lane >> 4) << 4));
            uint32_t a[2][4];
            #pragma unroll
            for (int i = 0; i < 2; i++) {
                int m = wm * 32 + i * 16 + (lane & 15);
                uint32_t addr = sA + (uint32_t)m * 128 + (col ^ (uint32_t)((m & 7) * 16));
                LDSM_X4(a[i][0], a[i][1], a[i][2], a[i][3], addr);
            }
            uint32_t b[8][2];
            #pragma unroll
            for (int jj = 0; jj < 4; jj++) {
                int n = wn * 64 + jj * 16 + (lane & 15);
                uint32_t addr = sB + (uint32_t)n * 128 + (col ^ (uint32_t)((n & 7) * 16));
                uint32_t r0, r1, r2, r3;
                LDSM_X4(r0, r1, r2, r3, addr);
                b[2*jj][0] = r0;   b[2*jj][1] = r2;
                b[2*jj+1][0] = r1; b[2*jj+1][1] = r3;
            }
            #pragma unroll
            for (int i = 0; i < 2; i++)
                #pragma unroll
                for (int j = 0; j < 8; j++)
                    MMA_BF16(d[i][j], a[i], b[j]);
        }
        __syncthreads();   // stage s free for reuse; gates next prefetch
    }

    #pragma unroll
    for (int i = 0; i < 2; i++) {
        int r0 = bm + wm * 32 + i * 16 + (lane >> 2);
        #pragma unroll
        for (int j = 0; j < 8; j++) {
            int gc = bn + wn * 64 + j * 8 + (lane & 3) * 2;
            float2 bv = bias ? *(const float2*)&bias[gc] : make_float2(0.f, 0.f);
            *(float2*)&C[(size_t)r0 * DD + gc] =
                make_float2(d[i][j][0] + bv.x, d[i][j][1] + bv.y);
            *(float2*)&C[(size_t)(r0 + 8) * DD + gc] =
                make_float2(d[i][j][2] + bv.x, d[i][j][3] + bv.y);
        }
    }
}

// ===========================================================================
// GEMM2 (tf32, ldmatrix): C[rows,768] = A @ B^T (+addmat). Tile 128x128, NCH=24.
// ===========================================================================
__global__ __launch_bounds__(256, 2) void gemm2_tf32_tma(
    const __grid_constant__ CUtensorMap mA,
    const __grid_constant__ CUtensorMap mB,
    float* __restrict__ C, const float* __restrict__ addmat, int rowOff)
{
    extern __shared__ __align__(1024) char smem[];
    const uint32_t sb = smem_u32(smem);
    const int tid = threadIdx.x, lane = tid & 31, wid = tid >> 5;
    const int wm = wid & 3, wn = wid >> 2;
    const int bm = rowOff + blockIdx.y * 128, bn = blockIdx.x * 128;
    const uint32_t fullb = sb;
    const uint32_t tiles = sb + 1024;
    const int NCH = 24;
    const int lt = lane >> 3;   // ldmatrix tile index 0..3
    const int lr = lane & 7;    // row within tile

    if (tid == 0) {
        #pragma unroll
        for (int s = 0; s < ST; s++) MBAR_INIT(fullb + 8*s, 1);
        asm volatile("fence.proxy.async.shared::cta;" ::: "memory");
    }
    __syncthreads();

    if (tid == 0) {
        #pragma unroll
        for (int s = 0; s < ST - 1; s++) {
            MBAR_EXPECT_TX(fullb + 8*s, STB);
            uint32_t dA = tiles + s * STB;
            TMA_2D(dA,         &mA, s * 32, bm, fullb + 8*s);
            TMA_2D(dA + 16384, &mB, s * 32, bn, fullb + 8*s);
        }
    }

    float d[2][8][4];
    #pragma unroll
    for (int i = 0; i < 2; i++)
        #pragma unroll
        for (int j = 0; j < 8; j++)
            #pragma unroll
            for (int k = 0; k < 4; k++) d[i][j][k] = 0.f;

    for (int it = 0; it < NCH; it++) {
        if (tid == 0) {
            int pre = it + ST - 1;
            if (pre < NCH) {
                int sp = pre % ST;
                MBAR_EXPECT_TX(fullb + 8*sp, STB);
                uint32_t dA = tiles + sp * STB;
                TMA_2D(dA,         &mA, pre * 32, bm, fullb + 8*sp);
                TMA_2D(dA + 16384, &mB, pre * 32, bn, fullb + 8*sp);
            }
        }
        int s = it % ST;
        MBAR_WAIT(fullb + 8*s, (it / ST) & 1);
        uint32_t sA = tiles + s * STB;
        uint32_t sB = sA + 16384;

        // 8x8 b16 ldmatrix tile == 8x4 fp32 tile; per-thread layout matches
        // the tf32 m16n8k8 fragment exactly.
        #pragma unroll
        for (int ks = 0; ks < 4; ks++) {
            uint32_t a[2][4];
            #pragma unroll
            for (int i = 0; i < 2; i++) {
                int m = wm * 32 + i * 16 + (lt & 1) * 8 + lr;
                uint32_t col = (uint32_t)(ks * 32 + (lt >> 1) * 16);
                uint32_t addr = sA + (uint32_t)m * 128 + (col ^ (uint32_t)((m & 7) * 16));
                LDSM_X4(a[i][0], a[i][1], a[i][2], a[i][3], addr);
            }
            uint32_t b[8][2];
            #pragma unroll
            for (int jj = 0; jj < 4; jj++) {
                int n = wn * 64 + jj * 16 + (lt >> 1) * 8 + lr;
                uint32_t col = (uint32_t)(ks * 32 + (lt & 1) * 16);
                uint32_t addr = sB + (uint32_t)n * 128 + (col ^ (uint32_t)((n & 7) * 16));
                uint32_t r0, r1, r2, r3;
                LDSM_X4(r0, r1, r2, r3, addr);
                b[2*jj][0] = r0;   b[2*jj][1] = r1;
                b[2*jj+1][0] = r2; b[2*jj+1][1] = r3;
            }
            #pragma unroll
            for (int i = 0; i < 2; i++)
                #pragma unroll
                for (int j = 0; j < 8; j++)
                    MMA_TF32(d[i][j], a[i], b[j]);
        }
        __syncthreads();
    }

    #pragma unroll
    for (int i = 0; i < 2; i++) {
        int r0 = bm + wm * 32 + i * 16 + (lane >> 2);
        #pragma unroll
        for (int j = 0; j < 8; j++) {
            int gc = bn + wn * 64 + j * 8 + (lane & 3) * 2;
            float2 a0 = make_float2(0.f, 0.f), a1 = make_float2(0.f, 0.f);
            if (addmat) {
                a0 = *(const float2*)&addmat[(size_t)r0 * DD + gc];
                a1 = *(const float2*)&addmat[(size_t)(r0 + 8) * DD + gc];
            }
            *(float2*)&C[(size_t)r0 * DD + gc] =
                make_float2(d[i][j][0] + a0.x, d[i][j][1] + a0.y);
            *(float2*)&C[(size_t)(r0 + 8) * DD + gc] =
                make_float2(d[i][j][2] + a1.x, d[i][j][3] + a1.y);
        }
    }
}

// ---------------------------------------------------------------------------
__global__ void prep_bp_kernel(const float* __restrict__ bq,
                               const float* __restrict__ Wk,
                               float* __restrict__ bp) {
    int n = blockIdx.x * blockDim.x + threadIdx.x;
    if (n >= DD) return;
    float acc = 0.f;
    #pragma unroll 4
    for (int i = 0; i < DD; i++) acc += bq[i] * Wk[i * DD + n];
    bp[n] = acc;
}

// fp32 -> bf16 elementwise (float4-wide)
__global__ void convb_kernel(const float4* __restrict__ in,
                             uint2* __restrict__ out, int n4) {
    int i = blockIdx.x * blockDim.x + threadIdx.x;
    if (i >= n4) return;
    float4 v = in[i];
    __nv_bfloat162 p0 = __floats2bfloat162_rn(v.x, v.y);
    __nv_bfloat162 p1 = __floats2bfloat162_rn(v.z, v.w);
    out[i] = make_uint2(*(uint32_t*)&p0, *(uint32_t*)&p1);
}

// fp32 -> tf32-rounded fp32 elementwise
__global__ void convt_kernel(const float4* __restrict__ in,
                             float4* __restrict__ out, int n4) {
    int i = blockIdx.x * blockDim.x + threadIdx.x;
    if (i >= n4) return;
    float4 v = in[i];
    out[i] = make_float4(tf32r(v.x), tf32r(v.y), tf32r(v.z), tf32r(v.w));
}

// transpose 768x768 + tf32 rounding (fp32 out)
__global__ void tconvt_kernel(const float* __restrict__ in,
                              float* __restrict__ out) {
    __shared__ float t[32][33];
    int bx = blockIdx.x * 32, by = blockIdx.y * 32;
    int tx = threadIdx.x, ty = threadIdx.y;   // 32 x 8
    #pragma unroll
    for (int i = 0; i < 4; i++)
        t[ty + i * 8][tx] = in[(size_t)(by + ty + i * 8) * DD + bx + tx];
    __syncthreads();
    #pragma unroll
    for (int i = 0; i < 4; i++)
        out[(size_t)(bx + ty + i * 8) * DD + by + tx] =
            tf32r(t[tx][ty + i * 8]);
}

// ---------------------------------------------------------------------------
// Attention: 192 threads, float4 lanes. ctx written tf32-rounded.
// ---------------------------------------------------------------------------
__global__ __launch_bounds__(192) void attn_kernel(
    const float* __restrict__ U,
    const float* __restrict__ key,
    const float* __restrict__ value,
    float* __restrict__ probs_out,
    float* __restrict__ ctx, int rowOff)
{
    const int row = rowOff + blockIdx.x;
    const int tid = threadIdx.x;               // 0..191
    const float4* u4 = (const float4*)(U + (size_t)row * DD);
    const float4* k4 = (const float4*)(key + (size_t)row * NN * DD);
    const float4* v4 = (const float4*)(value + (size_t)row * NN * DD);

    const float4 u = u4[tid];

    float p[NN];
    #pragma unroll
    for (int n = 0; n < NN; n++) {
        float4 k = k4[n * 192 + tid];
        p[n] = u.x * k.x + u.y * k.y + u.z * k.z + u.w * k.w;
    }
    #pragma unroll
    for (int n = 0; n < NN; n++)
        #pragma unroll
        for (int off = 16; off > 0; off >>= 1)
            p[n] += __shfl_down_sync(0xffffffffu, p[n], off);

    __shared__ float red[6][NN];
    __shared__ float probs[NN];
    const int lane = tid & 31, w = tid >> 5;
    if (lane == 0) {
        #pragma unroll
        for (int n = 0; n < NN; n++) red[w][n] = p[n];
    }
    __syncthreads();

    if (tid == 0) {
        float s[NN];
        #pragma unroll
        for (int n = 0; n < NN; n++) {
            float acc = 0.f;
            #pragma unroll
            for (int ww = 0; ww < 6; ww++) acc += red[ww][n];
            s[n] = acc;
        }
        float m = s[0];
        #pragma unroll
        for (int n = 1; n < NN; n++) m = fmaxf(m, s[n]);
        float e[NN], sum = 0.f;
        #pragma unroll
        for (int n = 0; n < NN; n++) { e[n] = expf((s[n] - m) * (1.0f / 50.0f)); sum += e[n]; }
        float inv = 1.f / sum;
        #pragma unroll
        for (int n = 0; n < NN; n++) probs[n] = e[n] * inv;
    }
    __syncthreads();

    if (tid < NN) probs_out[(size_t)row * NN + tid] = probs[tid];

    float pr[NN];
    #pragma unroll
    for (int n = 0; n < NN; n++) pr[n] = probs[n];

    float4 acc = make_float4(0.f, 0.f, 0.f, 0.f);
    #pragma unroll
    for (int n = 0; n < NN; n++) {
        float4 v = v4[n * 192 + tid];
        acc.x += pr[n] * v.x; acc.y += pr[n] * v.y;
        acc.z += pr[n] * v.z; acc.w += pr[n] * v.w;
    }
    ((float4*)(ctx + (size_t)row * DD))[tid] =
        make_float4(tf32r(acc.x), tf32r(acc.y), tf32r(acc.z), tf32r(acc.w));
}

// ---------------------------------------------------------------------------
typedef CUresult (*EncodeFn)(CUtensorMap*, CUtensorMapDataType, cuuint32_t, void*,
                             const cuuint64_t*, const cuuint64_t*, const cuuint32_t*,
                             const cuuint32_t*, CUtensorMapInterleave, CUtensorMapSwizzle,
                             CUtensorMapL2promotion, CUtensorMapFloatOOBfill);

static void make_map2d(EncodeFn enc, CUtensorMap* m, void* ptr,
                       CUtensorMapDataType dt, int elsz,
                       uint64_t d0, uint64_t d1, uint32_t b0, uint32_t b1) {
    cuuint64_t dims[2]    = {d0, d1};
    cuuint64_t strides[1] = {d0 * (uint64_t)elsz};
    cuuint32_t box[2]     = {b0, b1};
    cuuint32_t es[2]      = {1, 1};
    enc(m, dt, 2, ptr, dims, strides, box, es,
        CU_TENSOR_MAP_INTERLEAVE_NONE, CU_TENSOR_MAP_SWIZZLE_128B,
        CU_TENSOR_MAP_L2_PROMOTION_L2_128B, CU_TENSOR_MAP_FLOAT_OOB_FILL_NONE);
}

extern "C" void kernel_launch(void* const* d_in, const int* in_sizes, int n_in,
                              void* d_out, int out_size) {
    const float* query    = (const float*)d_in[0];
    const float* key      = (const float*)d_in[1];
    const float* value    = (const float*)d_in[2];
    const float* residual = (const float*)d_in[3];
    const float* Wq       = (const float*)d_in[4];
    const float* bq       = (const float*)d_in[5];
    const float* Wk       = (const float*)d_in[6];
    // d_in[7] = bk: constant logit shift across heads -> dropped by softmax
    const float* Wv       = (const float*)d_in[8];

    float* out       = (float*)d_out;
    float* probs_out = out;
    float* ctx_out   = out + (size_t)ROWS * NN;

    float *U, *ctx, *Wpp, *WkT32, *WqT32, *Wv32, *bp;
    __nv_bfloat16 *qb, *Wppb;
    cudaGetSymbolAddress((void**)&U,     g_U);
    cudaGetSymbolAddress((void**)&ctx,   g_ctx);
    cudaGetSymbolAddress((void**)&qb,    g_qb);
    cudaGetSymbolAddress((void**)&Wppb,  g_Wppb);
    cudaGetSymbolAddress((void**)&Wpp,   g_Wpp);
    cudaGetSymbolAddress((void**)&WkT32, g_WkT32);
    cudaGetSymbolAddress((void**)&WqT32, g_WqT32);
    cudaGetSymbolAddress((void**)&Wv32,  g_Wv32);
    cudaGetSymbolAddress((void**)&bp,    g_bp);

    cudaFuncSetAttribute(gemm1_bf16_tma,
                         cudaFuncAttributeMaxDynamicSharedMemorySize, GSMEM);
    cudaFuncSetAttribute(gemm2_tf32_tma,
                         cudaFuncAttributeMaxDynamicSharedMemorySize, GSMEM);

    EncodeFn enc = nullptr;
    cudaDriverEntryPointQueryResult qr;
    cudaGetDriverEntryPointByVersion("cuTensorMapEncodeTiled", (void**)&enc,
                                     12000, cudaEnableDefault, &qr);

    CUtensorMap mQ, mWpp, mCtx, mWv, mWkT, mWqT;
    make_map2d(enc, &mQ,   qb,    CU_TENSOR_MAP_DATA_TYPE_BFLOAT16, 2, DD, ROWS, 64, 128);
    make_map2d(enc, &mWpp, Wppb,  CU_TENSOR_MAP_DATA_TYPE_BFLOAT16, 2, DD, DD,   64, 128);
    make_map2d(enc, &mWkT, WkT32, CU_TENSOR_MAP_DATA_TYPE_FLOAT32,  4, DD, DD,   32, 128);
    make_map2d(enc, &mWqT, WqT32, CU_TENSOR_MAP_DATA_TYPE_FLOAT32,  4, DD, DD,   32, 128);
    make_map2d(enc, &mCtx, ctx,   CU_TENSOR_MAP_DATA_TYPE_FLOAT32,  4, DD, ROWS, 32, 128);
    make_map2d(enc, &mWv,  Wv32,  CU_TENSOR_MAP_DATA_TYPE_FLOAT32,  4, DD, DD,   32, 128);

    // Streams + events. Created on the first (uncaptured, correctness) call;
    // reused afterwards. Side streams join the capture only via
    // StreamWaitEvent on an event recorded in a captured stream (evRoot).
    static cudaStream_t sAttn = nullptr, sG2 = nullptr, sAux = nullptr;
    static cudaEvent_t evG1, evA[CHUNKS], evRoot, evQ, evDone;
    if (!sAttn) {
        cudaStreamCreateWithFlags(&sAttn, cudaStreamNonBlocking);
        cudaStreamCreateWithFlags(&sG2,   cudaStreamNonBlocking);
        cudaStreamCreateWithFlags(&sAux,  cudaStreamNonBlocking);
        for (int i = 0; i < CHUNKS; i++)
            cudaEventCreateWithFlags(&evA[i], cudaEventDisableTiming);
        cudaEventCreateWithFlags(&evG1,   cudaEventDisableTiming);
        cudaEventCreateWithFlags(&evRoot, cudaEventDisableTiming);
        cudaEventCreateWithFlags(&evQ,    cudaEventDisableTiming);
        cudaEventCreateWithFlags(&evDone, cudaEventDisableTiming);
    }

    dim3 tgrid(DD / 32, DD / 32);

    // ---- fork side streams from the capture origin ----
    cudaEventRecord(evRoot, 0);
    cudaStreamWaitEvent(sAux, evRoot, 0);
    cudaStreamWaitEvent(sG2,  evRoot, 0);

    // sAux: query -> bf16 (gemm1's A operand)
    convb_kernel<<<(ROWS * DD / 4 + 255) / 256, 256, 0, sAux>>>(
        (const float4*)query, (uint2*)qb, ROWS * DD / 4);
    cudaEventRecord(evQ, sAux);

    // sG2: Wv tf32-round (only consumer is gemm2, same stream -> ordered)
    convt_kernel<<<(DD * DD / 4 + 255) / 256, 256, 0, sG2>>>(
        (const float4*)Wv, (float4*)Wv32, DD * DD / 4);

    // stream 0: bp + W'' chain (gemm1's other inputs)
    prep_bp_kernel<<<6, 128>>>(bq, Wk, bp);
    tconvt_kernel<<<tgrid, dim3(32, 8)>>>(Wk, WkT32);
    tconvt_kernel<<<tgrid, dim3(32, 8)>>>(Wq, WqT32);
    gemm2_tf32_tma<<<dim3(6, 6), 256, GSMEM>>>(mWkT, mWqT, Wpp, nullptr, 0);
    convb_kernel<<<(DD * DD / 4 + 255) / 256, 256>>>(
        (const float4*)Wpp, (uint2*)Wppb, DD * DD / 4);
    cudaStreamWaitEvent(0, evQ, 0);   // qb ready before gemm1

    // ---- gemm1: full grid (768 CTAs), maximal efficiency ----
    gemm1_bf16_tma<<<dim3(6, ROWS / 128), 256, GSMEM>>>(mQ, mWpp, U, bp, 0);
    cudaEventRecord(evG1, 0);
    cudaStreamWaitEvent(sAttn, evG1, 0);

    // ---- 2-chunk attn -> gemm2 overlap: attn_1 co-runs with gemm2_0 ----
    for (int i = 0; i < CHUNKS; i++) {
        int ro = i * CROWS;
        attn_kernel<<<CROWS, 192, 0, sAttn>>>(U, key, value, probs_out, ctx, ro);
        cudaEventRecord(evA[i], sAttn);

        cudaStreamWaitEvent(sG2, evA[i], 0);
        gemm2_tf32_tma<<<dim3(6, CROWS / 128), 256, GSMEM, sG2>>>(
            mCtx, mWv, ctx_out, residual, ro);
    }

    // join everything back to the default stream
    cudaEventRecord(evDone, sG2);
    cudaStreamWaitEvent(0, evDone, 0);
}

// round 17
// speedup vs baseline: 1.0935x; 1.0491x over previous
#include <cuda_runtime.h>
#include <cuda.h>
#include <cuda_bf16.h>
#include <cstdint>

#define BB 8
#define SS 2048
#define NN 8
#define DD 768
#define ROWS (BB*SS)          // 16384
#define CHUNKS 4
#define CROWS (ROWS/CHUNKS)   // 4096

__device__ __align__(256) float         g_U[ROWS*DD];
__device__ __align__(256) float         g_ctx[ROWS*DD];    // tf32-rounded
__device__ __align__(256) __nv_bfloat16 g_qb[ROWS*DD];
__device__ __align__(256) __nv_bfloat16 g_Wppb[DD*DD];     // [n,k] bf16 (written by gemm2 directly)
__device__ __align__(256) float         g_WkT32[DD*DD];    // Wk^T tf32-rounded
__device__ __align__(256) float         g_WqT32[DD*DD];    // Wq^T tf32-rounded
__device__ __align__(256) float         g_Wv32[DD*DD];     // Wv tf32-rounded
__device__ __align__(256) float         g_bp[DD];

// ======================= portable PTX helpers (<= sm_90) ====================
__device__ __forceinline__ uint32_t smem_u32(const void* p) {
    uint32_t a;
    asm("{ .reg .u64 t; cvta.to.shared.u64 t, %1; cvt.u32.u64 %0, t; }"
        : "=r"(a) : "l"(p));
    return a;
}

#define MBAR_INIT(addr, cnt) \
    asm volatile("mbarrier.init.shared.b64 [%0], %1;" :: "r"((uint32_t)(addr)), "r"((uint32_t)(cnt)) : "memory")
#define MBAR_EXPECT_TX(addr, bytes) \
    asm volatile("mbarrier.arrive.expect_tx.shared.b64 _, [%0], %1;" \
                 :: "r"((uint32_t)(addr)), "r"((uint32_t)(bytes)) : "memory")

#define MBAR_WAIT(mbar_addr, phase_parity) do {                                   \
    uint32_t _mbar = (uint32_t)(mbar_addr);                                        \
    uint32_t _par  = (uint32_t)(phase_parity);                                     \
    uint32_t _done;                                                                \
    asm volatile(                                                                  \
        "{\n\t.reg .pred p;\n\t"                                                   \
        "mbarrier.try_wait.parity.acquire.cta.shared::cta.b64 p, [%1], %2;\n\t"    \
        "selp.b32 %0, 1, 0, p;\n\t}"                                               \
        : "=r"(_done) : "r"(_mbar), "r"(_par) : "memory");                         \
    if (!_done) {                                                                  \
        asm volatile(                                                              \
            "{\n\t.reg .pred P1;\n\t"                                              \
            "WAIT_LOOP_%=:\n\t"                                                    \
            "mbarrier.try_wait.parity.acquire.cta.shared::cta.b64 P1, [%0], %1, 0x989680;\n\t" \
            "@P1 bra.uni WAIT_DONE_%=;\n\t"                                        \
            "bra.uni WAIT_LOOP_%=;\n\t"                                            \
            "WAIT_DONE_%=:\n\t}"                                                   \
            :: "r"(_mbar), "r"(_par) : "memory");                                  \
    }                                                                              \
} while (0)

#define TMA_2D(dst, map, x, y, mbar) \
    asm volatile("cp.async.bulk.tensor.2d.shared::cluster.global.tile.mbarrier::complete_tx::bytes " \
        "[%0], [%1, {%2, %3}], [%4];" \
        :: "r"((uint32_t)(dst)), "l"(map), "r"((int)(x)), "r"((int)(y)), \
           "r"((uint32_t)(mbar)) : "memory")

#define LDSM_X4(r0, r1, r2, r3, addr) \
    asm volatile("ldmatrix.sync.aligned.m8n8.x4.shared.b16 {%0,%1,%2,%3}, [%4];" \
        : "=r"(r0), "=r"(r1), "=r"(r2), "=r"(r3) : "r"((uint32_t)(addr)))

#define MMA_BF16(d, a, b) \
    asm volatile("mma.sync.aligned.m16n8k16.row.col.f32.bf16.bf16.f32 " \
        "{%0,%1,%2,%3}, {%4,%5,%6,%7}, {%8,%9}, {%0,%1,%2,%3};" \
        : "+f"((d)[0]), "+f"((d)[1]), "+f"((d)[2]), "+f"((d)[3]) \
        : "r"((a)[0]), "r"((a)[1]), "r"((a)[2]), "r"((a)[3]), \
          "r"((b)[0]), "r"((b)[1]))

#define MMA_TF32(d, a, b) \
    asm volatile("mma.sync.aligned.m16n8k8.row.col.f32.tf32.tf32.f32 " \
        "{%0,%1,%2,%3}, {%4,%5,%6,%7}, {%8,%9}, {%0,%1,%2,%3};" \
        : "+f"((d)[0]), "+f"((d)[1]), "+f"((d)[2]), "+f"((d)[3]) \
        : "r"((a)[0]), "r"((a)[1]), "r"((a)[2]), "r"((a)[3]), \
          "r"((b)[0]), "r"((b)[1]))

__device__ __forceinline__ float tf32r(float f) {
    uint32_t u;
    asm("cvt.rna.tf32.f32 %0, %1;" : "=r"(u) : "f"(f));
    return __uint_as_float(u);
}

// Pipeline: 3 stages x (16KB A + 16KB B); syncthreads-gated reuse.
#define ST 3
#define STB 32768
#define GSMEM (1024 + ST * STB)

// ===========================================================================
// GEMM1 (bf16): C[rows,768] = A @ B^T (+bias). Tile 128x128, K-chunk 64.
// ===========================================================================
__global__ __launch_bounds__(256, 2) void gemm1_bf16_tma(
    const __grid_constant__ CUtensorMap mA,
    const __grid_constant__ CUtensorMap mB,
    float* __restrict__ C, const float* __restrict__ bias, int rowOff)
{
    extern __shared__ __align__(1024) char smem[];
    const uint32_t sb = smem_u32(smem);
    const int tid = threadIdx.x, lane = tid & 31, wid = tid >> 5;
    const int wm = wid & 3, wn = wid >> 2;
    const int bm = rowOff + blockIdx.y * 128, bn = blockIdx.x * 128;
    const uint32_t fullb = sb;
    const uint32_t tiles = sb + 1024;
    const int NCH = 12;

    if (tid == 0) {
        #pragma unroll
        for (int s = 0; s < ST; s++) MBAR_INIT(fullb + 8*s, 1);
        asm volatile("fence.proxy.async.shared::cta;" ::: "memory");
    }
    __syncthreads();

    if (tid == 0) {
        #pragma unroll
        for (int s = 0; s < ST - 1; s++) {
            MBAR_EXPECT_TX(fullb + 8*s, STB);
            uint32_t dA = tiles + s * STB;
            TMA_2D(dA,         &mA, s * 64, bm, fullb + 8*s);
            TMA_2D(dA + 16384, &mB, s * 64, bn, fullb + 8*s);
        }
    }

    float d[2][8][4];
    #pragma unroll
    for (int i = 0; i < 2; i++)
        #pragma unroll
        for (int j = 0; j < 8; j++)
            #pragma unroll
            for (int k = 0; k < 4; k++) d[i][j][k] = 0.f;

    for (int it = 0; it < NCH; it++) {
        if (tid == 0) {
            int pre = it + ST - 1;
            if (pre < NCH) {
                int sp = pre % ST;
                MBAR_EXPECT_TX(fullb + 8*sp, STB);
                uint32_t dA = tiles + sp * STB;
                TMA_2D(dA,         &mA, pre * 64, bm, fullb + 8*sp);
                TMA_2D(dA + 16384, &mB, pre * 64, bn, fullb + 8*sp);
            }
        }
        int s = it % ST;
        MBAR_WAIT(fullb + 8*s, (it / ST) & 1);
        uint32_t sA = tiles + s * STB;
        uint32_t sB = sA + 16384;

        #pragma unroll
        for (int ks = 0; ks < 4; ks++) {
            uint32_t col = (uint32_t)(ks * 32 + ((lane >> 4) << 4));
            uint32_t a[2][4];
            #pragma unroll
            for (int i = 0; i < 2; i++) {
                int m = wm * 32 + i * 16 + (lane & 15);
                uint32_t addr = sA + (uint32_t)m * 128 + (col ^ (uint32_t)((m & 7) * 16));
                LDSM_X4(a[i][0], a[i][1], a[i][2], a[i][3], addr);
            }
            uint32_t b[8][2];
            #pragma unroll
            for (int jj = 0; jj < 4; jj++) {
                int n = wn * 64 + jj * 16 + (lane & 15);
                uint32_t addr = sB + (uint32_t)n * 128 + (col ^ (uint32_t)((n & 7) * 16));
                uint32_t r0, r1, r2, r3;
                LDSM_X4(r0, r1, r2, r3, addr);
                b[2*jj][0] = r0;   b[2*jj][1] = r2;
                b[2*jj+1][0] = r1; b[2*jj+1][1] = r3;
            }
            #pragma unroll
            for (int i = 0; i < 2; i++)
                #pragma unroll
                for (int j = 0; j < 8; j++)
                    MMA_BF16(d[i][j], a[i], b[j]);
        }
        __syncthreads();   // stage s free for reuse; gates next prefetch
    }

    #pragma unroll
    for (int i = 0; i < 2; i++) {
        int r0 = bm + wm * 32 + i * 16 + (lane >> 2);
        #pragma unroll
        for (int j = 0; j < 8; j++) {
            int gc = bn + wn * 64 + j * 8 + (lane & 3) * 2;
            float2 bv = bias ? *(const float2*)&bias[gc] : make_float2(0.f, 0.f);
            *(float2*)&C[(size_t)r0 * DD + gc] =
                make_float2(d[i][j][0] + bv.x, d[i][j][1] + bv.y);
            *(float2*)&C[(size_t)(r0 + 8) * DD + gc] =
                make_float2(d[i][j][2] + bv.x, d[i][j][3] + bv.y);
        }
    }
}

// ===========================================================================
// GEMM2 (tf32, ldmatrix): C[rows,768] = A @ B^T (+addmat). Tile 128x128, NCH=24.
// A, B pre-rounded to tf32 in global memory. addmat nullable.
// bf16out: store bf16 (rn) instead of fp32 — used for W'' so the separate
// conversion kernel disappears; values are bit-identical to convb's output.
// ===========================================================================
__global__ __launch_bounds__(256, 2) void gemm2_tf32_tma(
    const __grid_constant__ CUtensorMap mA,
    const __grid_constant__ CUtensorMap mB,
    void* __restrict__ Cout, const float* __restrict__ addmat,
    int rowOff, int bf16out)
{
    extern __shared__ __align__(1024) char smem[];
    const uint32_t sb = smem_u32(smem);
    const int tid = threadIdx.x, lane = tid & 31, wid = tid >> 5;
    const int wm = wid & 3, wn = wid >> 2;
    const int bm = rowOff + blockIdx.y * 128, bn = blockIdx.x * 128;
    const uint32_t fullb = sb;
    const uint32_t tiles = sb + 1024;
    const int NCH = 24;
    const int lt = lane >> 3;   // ldmatrix tile index 0..3
    const int lr = lane & 7;    // row within tile

    if (tid == 0) {
        #pragma unroll
        for (int s = 0; s < ST; s++) MBAR_INIT(fullb + 8*s, 1);
        asm volatile("fence.proxy.async.shared::cta;" ::: "memory");
    }
    __syncthreads();

    if (tid == 0) {
        #pragma unroll
        for (int s = 0; s < ST - 1; s++) {
            MBAR_EXPECT_TX(fullb + 8*s, STB);
            uint32_t dA = tiles + s * STB;
            TMA_2D(dA,         &mA, s * 32, bm, fullb + 8*s);
            TMA_2D(dA + 16384, &mB, s * 32, bn, fullb + 8*s);
        }
    }

    float d[2][8][4];
    #pragma unroll
    for (int i = 0; i < 2; i++)
        #pragma unroll
        for (int j = 0; j < 8; j++)
            #pragma unroll
            for (int k = 0; k < 4; k++) d[i][j][k] = 0.f;

    for (int it = 0; it < NCH; it++) {
        if (tid == 0) {
            int pre = it + ST - 1;
            if (pre < NCH) {
                int sp = pre % ST;
                MBAR_EXPECT_TX(fullb + 8*sp, STB);
                uint32_t dA = tiles + sp * STB;
                TMA_2D(dA,         &mA, pre * 32, bm, fullb + 8*sp);
                TMA_2D(dA + 16384, &mB, pre * 32, bn, fullb + 8*sp);
            }
        }
        int s = it % ST;
        MBAR_WAIT(fullb + 8*s, (it / ST) & 1);
        uint32_t sA = tiles + s * STB;
        uint32_t sB = sA + 16384;

        // 8x8 b16 ldmatrix tile == 8x4 fp32 tile; per-thread layout matches
        // the tf32 m16n8k8 fragment exactly.
        #pragma unroll
        for (int ks = 0; ks < 4; ks++) {
            uint32_t a[2][4];
            #pragma unroll
            for (int i = 0; i < 2; i++) {
                int m = wm * 32 + i * 16 + (lt & 1) * 8 + lr;
                uint32_t col = (uint32_t)(ks * 32 + (lt >> 1) * 16);
                uint32_t addr = sA + (uint32_t)m * 128 + (col ^ (uint32_t)((m & 7) * 16));
                LDSM_X4(a[i][0], a[i][1], a[i][2], a[i][3], addr);
            }
            uint32_t b[8][2];
            #pragma unroll
            for (int jj = 0; jj < 4; jj++) {
                int n = wn * 64 + jj * 16 + (lt >> 1) * 8 + lr;
                uint32_t col = (uint32_t)(ks * 32 + (lt & 1) * 16);
                uint32_t addr = sB + (uint32_t)n * 128 + (col ^ (uint32_t)((n & 7) * 16));
                uint32_t r0, r1, r2, r3;
                LDSM_X4(r0, r1, r2, r3, addr);
                b[2*jj][0] = r0;   b[2*jj][1] = r1;
                b[2*jj+1][0] = r2; b[2*jj+1][1] = r3;
            }
            #pragma unroll
            for (int i = 0; i < 2; i++)
                #pragma unroll
                for (int j = 0; j < 8; j++)
                    MMA_TF32(d[i][j], a[i], b[j]);
        }
        __syncthreads();
    }

    #pragma unroll
    for (int i = 0; i < 2; i++) {
        int r0 = bm + wm * 32 + i * 16 + (lane >> 2);
        #pragma unroll
        for (int j = 0; j < 8; j++) {
            int gc = bn + wn * 64 + j * 8 + (lane & 3) * 2;
            float2 a0 = make_float2(0.f, 0.f), a1 = make_float2(0.f, 0.f);
            if (addmat) {
                a0 = *(const float2*)&addmat[(size_t)r0 * DD + gc];
                a1 = *(const float2*)&addmat[(size_t)(r0 + 8) * DD + gc];
            }
            float2 v0 = make_float2(d[i][j][0] + a0.x, d[i][j][1] + a0.y);
            float2 v1 = make_float2(d[i][j][2] + a1.x, d[i][j][3] + a1.y);
            if (bf16out) {
                __nv_bfloat16* Cb = (__nv_bfloat16*)Cout;
                __nv_bfloat162 p0 = __floats2bfloat162_rn(v0.x, v0.y);
                __nv_bfloat162 p1 = __floats2bfloat162_rn(v1.x, v1.y);
                *(uint32_t*)&Cb[(size_t)r0 * DD + gc]       = *(uint32_t*)&p0;
                *(uint32_t*)&Cb[(size_t)(r0 + 8) * DD + gc] = *(uint32_t*)&p1;
            } else {
                float* C = (float*)Cout;
                *(float2*)&C[(size_t)r0 * DD + gc]       = v0;
                *(float2*)&C[(size_t)(r0 + 8) * DD + gc] = v1;
            }
        }
    }
}

// ---------------------------------------------------------------------------
__global__ void prep_bp_kernel(const float* __restrict__ bq,
                               const float* __restrict__ Wk,
                               float* __restrict__ bp) {
    int n = blockIdx.x * blockDim.x + threadIdx.x;
    if (n >= DD) return;
    float acc = 0.f;
    #pragma unroll 4
    for (int i = 0; i < DD; i++) acc += bq[i] * Wk[i * DD + n];
    bp[n] = acc;
}

// fp32 -> bf16 elementwise (float4-wide)
__global__ void convb_kernel(const float4* __restrict__ in,
                             uint2* __restrict__ out, int n4) {
    int i = blockIdx.x * blockDim.x + threadIdx.x;
    if (i >= n4) return;
    float4 v = in[i];
    __nv_bfloat162 p0 = __floats2bfloat162_rn(v.x, v.y);
    __nv_bfloat162 p1 = __floats2bfloat162_rn(v.z, v.w);
    out[i] = make_uint2(*(uint32_t*)&p0, *(uint32_t*)&p1);
}

// Fused weight prep: z=0: WkT32 = tf32(Wk^T); z=1: WqT32 = tf32(Wq^T);
// z=2: Wv32 = tf32(Wv) (elementwise, same block geometry).
__global__ void prep_weights_kernel(const float* __restrict__ Wk,
                                    const float* __restrict__ Wq,
                                    const float* __restrict__ Wv,
                                    float* __restrict__ WkT32,
                                    float* __restrict__ WqT32,
                                    float* __restrict__ Wv32) {
    __shared__ float t[32][33];
    int bx = blockIdx.x * 32, by = blockIdx.y * 32;
    int tx = threadIdx.x, ty = threadIdx.y;   // 32 x 8
    int z = blockIdx.z;
    if (z == 2) {
        #pragma unroll
        for (int i = 0; i < 4; i++) {
            size_t idx = (size_t)(by + ty + i * 8) * DD + bx + tx;
            Wv32[idx] = tf32r(Wv[idx]);
        }
        return;
    }
    const float* in  = (z == 0) ? Wk : Wq;
    float*       out = (z == 0) ? WkT32 : WqT32;
    #pragma unroll
    for (int i = 0; i < 4; i++)
        t[ty + i * 8][tx] = in[(size_t)(by + ty + i * 8) * DD + bx + tx];
    __syncthreads();
    #pragma unroll
    for (int i = 0; i < 4; i++)
        out[(size_t)(bx + ty + i * 8) * DD + by + tx] =
            tf32r(t[tx][ty + i * 8]);
}

// ---------------------------------------------------------------------------
// Attention: 192 threads, float4 lanes. ctx written tf32-rounded.
// ---------------------------------------------------------------------------
__global__ __launch_bounds__(192) void attn_kernel(
    const float* __restrict__ U,
    const float* __restrict__ key,
    const float* __restrict__ value,
    float* __restrict__ probs_out,
    float* __restrict__ ctx, int rowOff)
{
    const int row = rowOff + blockIdx.x;
    const int tid = threadIdx.x;               // 0..191
    const float4* u4 = (const float4*)(U + (size_t)row * DD);
    const float4* k4 = (const float4*)(key + (size_t)row * NN * DD);
    const float4* v4 = (const float4*)(value + (size_t)row * NN * DD);

    const float4 u = u4[tid];

    float p[NN];
    #pragma unroll
    for (int n = 0; n < NN; n++) {
        float4 k = k4[n * 192 + tid];
        p[n] = u.x * k.x + u.y * k.y + u.z * k.z + u.w * k.w;
    }
    #pragma unroll
    for (int n = 0; n < NN; n++)
        #pragma unroll
        for (int off = 16; off > 0; off >>= 1)
            p[n] += __shfl_down_sync(0xffffffffu, p[n], off);

    __shared__ float red[6][NN];
    __shared__ float probs[NN];
    const int lane = tid & 31, w = tid >> 5;
    if (lane == 0) {
        #pragma unroll
        for (int n = 0; n < NN; n++) red[w][n] = p[n];
    }
    __syncthreads();

    if (tid == 0) {
        float s[NN];
        #pragma unroll
        for (int n = 0; n < NN; n++) {
            float acc = 0.f;
            #pragma unroll
            for (int ww = 0; ww < 6; ww++) acc += red[ww][n];
            s[n] = acc;
        }
        float m = s[0];
        #pragma unroll
        for (int n = 1; n < NN; n++) m = fmaxf(m, s[n]);
        float e[NN], sum = 0.f;
        #pragma unroll
        for (int n = 0; n < NN; n++) { e[n] = expf((s[n] - m) * (1.0f / 50.0f)); sum += e[n]; }
        float inv = 1.f / sum;
        #pragma unroll
        for (int n = 0; n < NN; n++) probs[n] = e[n] * inv;
    }
    __syncthreads();

    if (tid < NN) probs_out[(size_t)row * NN + tid] = probs[tid];

    float pr[NN];
    #pragma unroll
    for (int n = 0; n < NN; n++) pr[n] = probs[n];

    float4 acc = make_float4(0.f, 0.f, 0.f, 0.f);
    #pragma unroll
    for (int n = 0; n < NN; n++) {
        float4 v = v4[n * 192 + tid];
        acc.x += pr[n] * v.x; acc.y += pr[n] * v.y;
        acc.z += pr[n] * v.z; acc.w += pr[n] * v.w;
    }
    ((float4*)(ctx + (size_t)row * DD))[tid] =
        make_float4(tf32r(acc.x), tf32r(acc.y), tf32r(acc.z), tf32r(acc.w));
}

// ---------------------------------------------------------------------------
typedef CUresult (*EncodeFn)(CUtensorMap*, CUtensorMapDataType, cuuint32_t, void*,
                             const cuuint64_t*, const cuuint64_t*, const cuuint32_t*,
                             const cuuint32_t*, CUtensorMapInterleave, CUtensorMapSwizzle,
                             CUtensorMapL2promotion, CUtensorMapFloatOOBfill);

static void make_map2d(EncodeFn enc, CUtensorMap* m, void* ptr,
                       CUtensorMapDataType dt, int elsz,
                       uint64_t d0, uint64_t d1, uint32_t b0, uint32_t b1) {
    cuuint64_t dims[2]    = {d0, d1};
    cuuint64_t strides[1] = {d0 * (uint64_t)elsz};
    cuuint32_t box[2]     = {b0, b1};
    cuuint32_t es[2]      = {1, 1};
    enc(m, dt, 2, ptr, dims, strides, box, es,
        CU_TENSOR_MAP_INTERLEAVE_NONE, CU_TENSOR_MAP_SWIZZLE_128B,
        CU_TENSOR_MAP_L2_PROMOTION_L2_128B, CU_TENSOR_MAP_FLOAT_OOB_FILL_NONE);
}

extern "C" void kernel_launch(void* const* d_in, const int* in_sizes, int n_in,
                              void* d_out, int out_size) {
    const float* query    = (const float*)d_in[0];
    const float* key      = (const float*)d_in[1];
    const float* value    = (const float*)d_in[2];
    const float* residual = (const float*)d_in[3];
    const float* Wq       = (const float*)d_in[4];
    const float* bq       = (const float*)d_in[5];
    const float* Wk       = (const float*)d_in[6];
    // d_in[7] = bk: constant logit shift across heads -> dropped by softmax
    const float* Wv       = (const float*)d_in[8];

    float* out       = (float*)d_out;
    float* probs_out = out;
    float* ctx_out   = out + (size_t)ROWS * NN;

    float *U, *ctx, *WkT32, *WqT32, *Wv32, *bp;
    __nv_bfloat16 *qb, *Wppb;
    cudaGetSymbolAddress((void**)&U,     g_U);
    cudaGetSymbolAddress((void**)&ctx,   g_ctx);
    cudaGetSymbolAddress((void**)&qb,    g_qb);
    cudaGetSymbolAddress((void**)&Wppb,  g_Wppb);
    cudaGetSymbolAddress((void**)&WkT32, g_WkT32);
    cudaGetSymbolAddress((void**)&WqT32, g_WqT32);
    cudaGetSymbolAddress((void**)&Wv32,  g_Wv32);
    cudaGetSymbolAddress((void**)&bp,    g_bp);

    cudaFuncSetAttribute(gemm1_bf16_tma,
                         cudaFuncAttributeMaxDynamicSharedMemorySize, GSMEM);
    cudaFuncSetAttribute(gemm2_tf32_tma,
                         cudaFuncAttributeMaxDynamicSharedMemorySize, GSMEM);

    EncodeFn enc = nullptr;
    cudaDriverEntryPointQueryResult qr;
    cudaGetDriverEntryPointByVersion("cuTensorMapEncodeTiled", (void**)&enc,
                                     12000, cudaEnableDefault, &qr);

    CUtensorMap mQ, mWpp, mCtx, mWv, mWkT, mWqT;
    make_map2d(enc, &mQ,   qb,    CU_TENSOR_MAP_DATA_TYPE_BFLOAT16, 2, DD, ROWS, 64, 128);
    make_map2d(enc, &mWpp, Wppb,  CU_TENSOR_MAP_DATA_TYPE_BFLOAT16, 2, DD, DD,   64, 128);
    make_map2d(enc, &mWkT, WkT32, CU_TENSOR_MAP_DATA_TYPE_FLOAT32,  4, DD, DD,   32, 128);
    make_map2d(enc, &mWqT, WqT32, CU_TENSOR_MAP_DATA_TYPE_FLOAT32,  4, DD, DD,   32, 128);
    make_map2d(enc, &mCtx, ctx,   CU_TENSOR_MAP_DATA_TYPE_FLOAT32,  4, DD, ROWS, 32, 128);
    make_map2d(enc, &mWv,  Wv32,  CU_TENSOR_MAP_DATA_TYPE_FLOAT32,  4, DD, DD,   32, 128);

    // Streams + events: exactly the R13 topology (proven best). Created on
    // the first (uncaptured, correctness) call; reused afterwards. Side
    // streams join the capture via waits on stream-0-recorded events.
    static cudaStream_t sAttn = nullptr, sG2 = nullptr;
    static cudaEvent_t evG1[CHUNKS], evA[CHUNKS], evDone;
    if (!sAttn) {
        cudaStreamCreateWithFlags(&sAttn, cudaStreamNonBlocking);
        cudaStreamCreateWithFlags(&sG2,   cudaStreamNonBlocking);
        for (int i = 0; i < CHUNKS; i++) {
            cudaEventCreateWithFlags(&evG1[i], cudaEventDisableTiming);
            cudaEventCreateWithFlags(&evA[i],  cudaEventDisableTiming);
        }
        cudaEventCreateWithFlags(&evDone, cudaEventDisableTiming);
    }

    // ---- prep (default stream, serial — R13 config) ----
    prep_bp_kernel<<<6, 128>>>(bq, Wk, bp);
    prep_weights_kernel<<<dim3(DD / 32, DD / 32, 3), dim3(32, 8)>>>(
        Wk, Wq, Wv, WkT32, WqT32, Wv32);
    convb_kernel<<<(ROWS * DD / 4 + 255) / 256, 256>>>(
        (const float4*)query, (uint2*)qb, ROWS * DD / 4);

    // W''[n,k] = sum_i Wk[i,n] * Wq[i,k] in tf32 -> bf16 stored directly
    gemm2_tf32_tma<<<dim3(6, 6), 256, GSMEM>>>(mWkT, mWqT, Wppb, nullptr, 0, 1);

    // ---- pipelined chunks: gemm1_i (0) -> attn_i (sAttn) -> gemm2_i (sG2)
    for (int i = 0; i < CHUNKS; i++) {
        int ro = i * CROWS;
        gemm1_bf16_tma<<<dim3(6, CROWS / 128), 256, GSMEM>>>(mQ, mWpp, U, bp, ro);
        cudaEventRecord(evG1[i], 0);

        cudaStreamWaitEvent(sAttn, evG1[i], 0);
        attn_kernel<<<CROWS, 192, 0, sAttn>>>(U, key, value, probs_out, ctx, ro);
        cudaEventRecord(evA[i], sAttn);

        cudaStreamWaitEvent(sG2, evA[i], 0);
        gemm2_tf32_tma<<<dim3(6, CROWS / 128), 256, GSMEM, sG2>>>(
            mCtx, mWv, ctx_out, residual, ro, 0);
    }

    // join everything back to the default stream
    cudaEventRecord(evDone, sG2);
    cudaStreamWaitEvent(0, evDone, 0);
}